// round 8
// baseline (speedup 1.0000x reference)
#include <cuda_runtime.h>
#include <math.h>

// Problem constants
#define BQ   4
#define NQ   4096
#define NKV  1024
#define CD   512
#define NH   8
#define HD   64

// Scratch (device globals: allocation-free rule)
__device__ float g_kv  [BQ * NKV * CD];        // 2M  floats
__device__ float g_q   [BQ * NH * NQ  * HD];   // 8M  floats, [b][h][n][d]
__device__ float g_k   [BQ * NH * NKV * HD];   // 2M  floats
__device__ float g_v   [BQ * NH * NKV * HD];   // 2M  floats
__device__ float g_attn[BQ * NQ * CD];         // 8M  floats, [b][n][h*64+d]

__device__ __forceinline__ float ex2(float x) {
    float r;
    asm("ex2.approx.f32 %0, %1;" : "=f"(r) : "f"(x));
    return r;
}

// ---------------------------------------------------------------------------
// Tiled GEMM: BM = TM*16 x 128 tile, 256 threads, per-thread TM x 8.
// N (row stride of B / C) fixed at 512.
// MODE 0: row-major store (C0). MODE 1: head-major scatter (C0).
// MODE 2: dual weights/outputs (B0/C0 for n<512, B1/C1 for n>=512), scatter.
// NB: log2(rows per batch) for the scatter decode.
// ---------------------------------------------------------------------------
template <int TM, int MODE, int NB>
__global__ __launch_bounds__(256)
void gemm_tile(const float* __restrict__ A,
               const float* __restrict__ B0, const float* __restrict__ B1,
               const float* __restrict__ bias0, const float* __restrict__ bias1,
               float* __restrict__ C0, float* __restrict__ C1, int K)
{
    constexpr int BM = TM * 16;
    __shared__ float As[16][BM + 4];   // [k][m] transposed, padded
    __shared__ float Bs[16][128];      // [k][n]

    const int m0 = blockIdx.y * BM;
    const int n0 = blockIdx.x * 128;

    const bool second = (MODE == 2) && (n0 >= 512);
    const float* Bm   = second ? B1 : B0;
    const float* bias = second ? bias1 : bias0;
    float*       Cout = second ? C1 : C0;
    const int    n0l  = second ? (n0 - 512) : n0;

    const int t  = threadIdx.x;
    const int tx = t & 15;
    const int ty = t >> 4;
    const int brow = t >> 4;
    const int bcol = (t & 15) * 8;

    int arow, ak;
    if (TM == 8) { arow = t >> 1; ak = (t & 1) * 8; }
    else         { arow = t >> 2; ak = (t & 3) * 4; }
    const float* Ap = A + (size_t)(m0 + arow) * K;

    float acc[TM][8];
#pragma unroll
    for (int i = 0; i < TM; i++)
#pragma unroll
        for (int j = 0; j < 8; j++) acc[i][j] = 0.f;

    for (int k0 = 0; k0 < K; k0 += 16) {
        if (TM == 8) {
            float4 a0 = *(const float4*)(Ap + k0 + ak);
            float4 a1 = *(const float4*)(Ap + k0 + ak + 4);
            As[ak + 0][arow] = a0.x; As[ak + 1][arow] = a0.y;
            As[ak + 2][arow] = a0.z; As[ak + 3][arow] = a0.w;
            As[ak + 4][arow] = a1.x; As[ak + 5][arow] = a1.y;
            As[ak + 6][arow] = a1.z; As[ak + 7][arow] = a1.w;
        } else {
            float4 a0 = *(const float4*)(Ap + k0 + ak);
            As[ak + 0][arow] = a0.x; As[ak + 1][arow] = a0.y;
            As[ak + 2][arow] = a0.z; As[ak + 3][arow] = a0.w;
        }
        const float* Brow = Bm + (size_t)(k0 + brow) * 512 + n0l + bcol;
        *(float4*)&Bs[brow][bcol]     = *(const float4*)Brow;
        *(float4*)&Bs[brow][bcol + 4] = *(const float4*)(Brow + 4);
        __syncthreads();

#pragma unroll
        for (int kk = 0; kk < 16; kk++) {
            float a[TM];
#pragma unroll
            for (int v = 0; v < TM / 4; v++) {
                float4 av = *(const float4*)&As[kk][ty * TM + v * 4];
                a[v * 4 + 0] = av.x; a[v * 4 + 1] = av.y;
                a[v * 4 + 2] = av.z; a[v * 4 + 3] = av.w;
            }
            float4 b0 = *(const float4*)&Bs[kk][tx * 8];
            float4 b1 = *(const float4*)&Bs[kk][tx * 8 + 4];
            float bb[8] = {b0.x, b0.y, b0.z, b0.w, b1.x, b1.y, b1.z, b1.w};
#pragma unroll
            for (int i = 0; i < TM; i++)
#pragma unroll
                for (int j = 0; j < 8; j++) acc[i][j] += a[i] * bb[j];
        }
        __syncthreads();
    }

    float bias_r[8];
    {
        float4 c0 = *(const float4*)&bias[n0l + tx * 8];
        float4 c1 = *(const float4*)&bias[n0l + tx * 8 + 4];
        bias_r[0] = c0.x; bias_r[1] = c0.y; bias_r[2] = c0.z; bias_r[3] = c0.w;
        bias_r[4] = c1.x; bias_r[5] = c1.y; bias_r[6] = c1.z; bias_r[7] = c1.w;
    }

    if (MODE == 0) {
#pragma unroll
        for (int i = 0; i < TM; i++) {
            const int m = m0 + ty * TM + i;
            float4 o0 = make_float4(acc[i][0] + bias_r[0], acc[i][1] + bias_r[1],
                                    acc[i][2] + bias_r[2], acc[i][3] + bias_r[3]);
            float4 o1 = make_float4(acc[i][4] + bias_r[4], acc[i][5] + bias_r[5],
                                    acc[i][6] + bias_r[6], acc[i][7] + bias_r[7]);
            *(float4*)&Cout[(size_t)m * 512 + n0l + tx * 8]     = o0;
            *(float4*)&Cout[(size_t)m * 512 + n0l + tx * 8 + 4] = o1;
        }
    } else {
        // head-major scatter: c = n0l + tx*8 + j, h = j (since base div by 8), d fixed
        const int d0 = (n0l + tx * 8) >> 3;
#pragma unroll
        for (int i = 0; i < TM; i++) {
            const int m  = m0 + ty * TM + i;
            const int bb2 = m >> NB;
            const int nn  = m & ((1 << NB) - 1);
#pragma unroll
            for (int j = 0; j < 8; j++) {
                Cout[((((size_t)(bb2 * NH + j)) << NB) + nn) * HD + d0] =
                    acc[i][j] + bias_r[j];
            }
        }
    }
}

// ---------------------------------------------------------------------------
// SR conv as GEMM with gathered A: M=4096 (b,i,j), K=2048 (di,dj,c), N=512.
// 64x128 tile, 4x8 per thread.
// ---------------------------------------------------------------------------
__global__ __launch_bounds__(256)
void conv_gemm(const float* __restrict__ x,
               const float* __restrict__ Wm,
               const float* __restrict__ bias,
               float* __restrict__ Cout)
{
    __shared__ float As[16][68];
    __shared__ float Bs[16][128];

    const int m0 = blockIdx.y * 64;
    const int n0 = blockIdx.x * 128;
    const int t  = threadIdx.x;
    const int tx = t & 15;
    const int ty = t >> 4;
    const int arow = t >> 2;
    const int ak   = (t & 3) * 4;
    const int brow = t >> 4;
    const int bcol = (t & 15) * 8;

    const int m   = m0 + arow;
    const int b   = m >> 10;
    const int rem = m & 1023;
    const int ii  = rem >> 5;
    const int jj  = rem & 31;

    float acc[4][8];
#pragma unroll
    for (int i = 0; i < 4; i++)
#pragma unroll
        for (int j = 0; j < 8; j++) acc[i][j] = 0.f;

    for (int k0 = 0; k0 < 2048; k0 += 16) {
        const int k   = k0 + ak;
        const int blk = k >> 9;
        const int c   = k & 511;
        const int di  = blk >> 1;
        const int dj  = blk & 1;
        float4 a0 = *(const float4*)&x[
            (size_t)((b * 64 + 2 * ii + di) * 64 + (2 * jj + dj)) * 512 + c];
        As[ak + 0][arow] = a0.x; As[ak + 1][arow] = a0.y;
        As[ak + 2][arow] = a0.z; As[ak + 3][arow] = a0.w;
        const float* Brow = Wm + (size_t)(k0 + brow) * 512 + n0 + bcol;
        *(float4*)&Bs[brow][bcol]     = *(const float4*)Brow;
        *(float4*)&Bs[brow][bcol + 4] = *(const float4*)(Brow + 4);
        __syncthreads();

#pragma unroll
        for (int kk = 0; kk < 16; kk++) {
            float4 av = *(const float4*)&As[kk][ty * 4];
            float4 b0 = *(const float4*)&Bs[kk][tx * 8];
            float4 b1 = *(const float4*)&Bs[kk][tx * 8 + 4];
            float a[4]  = {av.x, av.y, av.z, av.w};
            float bb[8] = {b0.x, b0.y, b0.z, b0.w, b1.x, b1.y, b1.z, b1.w};
#pragma unroll
            for (int i = 0; i < 4; i++)
#pragma unroll
                for (int j = 0; j < 8; j++) acc[i][j] += a[i] * bb[j];
        }
        __syncthreads();
    }

#pragma unroll
    for (int i = 0; i < 4; i++) {
        const int mm = m0 + ty * 4 + i;
        float4 o0 = make_float4(acc[i][0] + bias[n0 + tx * 8 + 0],
                                acc[i][1] + bias[n0 + tx * 8 + 1],
                                acc[i][2] + bias[n0 + tx * 8 + 2],
                                acc[i][3] + bias[n0 + tx * 8 + 3]);
        float4 o1 = make_float4(acc[i][4] + bias[n0 + tx * 8 + 4],
                                acc[i][5] + bias[n0 + tx * 8 + 5],
                                acc[i][6] + bias[n0 + tx * 8 + 6],
                                acc[i][7] + bias[n0 + tx * 8 + 7]);
        *(float4*)&Cout[(size_t)mm * 512 + n0 + tx * 8]     = o0;
        *(float4*)&Cout[(size_t)mm * 512 + n0 + tx * 8 + 4] = o1;
    }
}

// ---------------------------------------------------------------------------
// LayerNorm in-place over the last dim (512) of g_kv. One block per row.
// ---------------------------------------------------------------------------
__global__ void ln_kernel(float* __restrict__ kv,
                          const float* __restrict__ gam,
                          const float* __restrict__ bet)
{
    __shared__ float red[256];
    const int row = blockIdx.x;
    const int t   = threadIdx.x;
    float* p = kv + (size_t)row * 512;

    float v0 = p[t], v1 = p[t + 256];
    red[t] = v0 + v1;
    __syncthreads();
    for (int o = 128; o > 0; o >>= 1) {
        if (t < o) red[t] += red[t + o];
        __syncthreads();
    }
    const float mu = red[0] * (1.f / 512.f);
    __syncthreads();

    const float d0 = v0 - mu, d1 = v1 - mu;
    red[t] = d0 * d0 + d1 * d1;
    __syncthreads();
    for (int o = 128; o > 0; o >>= 1) {
        if (t < o) red[t] += red[t + o];
        __syncthreads();
    }
    const float var = red[0] * (1.f / 512.f);
    const float r   = rsqrtf(var + 1e-6f);
    p[t]       = d0 * r * gam[t]       + bet[t];
    p[t + 256] = d1 * r * gam[t + 256] + bet[t + 256];
}

// ---------------------------------------------------------------------------
// Flash attention: one block per (b, h, 64-q tile). 128 threads, 8x4/thread.
// Qt/Kt transposed [d][n]; P stored transposed [k][q] for vector PV loads.
// Base-2 softmax: Q pre-scaled by 0.125*log2(e), exp via ex2.approx.
// ---------------------------------------------------------------------------
#define FQT 0          // Qt[64][68]
#define FKT 4352       // Kt[64][68]
#define FSS 8704       // Ss[64][68] transposed [k][q]
#define FVS 13056      // Vs[64][68]
#define FTOT 17408

__global__ __launch_bounds__(128)
void flash_kernel(const float* __restrict__ Q,
                  const float* __restrict__ Kk,
                  const float* __restrict__ V,
                  float* __restrict__ Out)
{
    extern __shared__ float sm[];
    float* Qt = sm + FQT;
    float* Kt = sm + FKT;
    float* Ss = sm + FSS;
    float* Vs = sm + FVS;

    const int b  = blockIdx.z;
    const int h  = blockIdx.y;
    const int qt = blockIdx.x;

    const float* Qp = Q  + ((size_t)(b * NH + h) * NQ + qt * 64) * HD;
    const float* Kp = Kk + (size_t)(b * NH + h) * NKV * HD;
    const float* Vp = V  + (size_t)(b * NH + h) * NKV * HD;

    const int t     = threadIdx.x;
    const int tx    = t & 15;
    const int ty    = t >> 4;          // 0..7
    const int lrow  = t >> 1;          // 0..63
    const int dbase = (t & 1) * 32;

    const float qscale = 0.125f * 1.44269504088896340736f;

#pragma unroll
    for (int u = 0; u < 8; u++) {
        float4 q4 = *(const float4*)&Qp[(size_t)lrow * HD + dbase + u * 4];
        Qt[(dbase + u * 4 + 0) * 68 + lrow] = q4.x * qscale;
        Qt[(dbase + u * 4 + 1) * 68 + lrow] = q4.y * qscale;
        Qt[(dbase + u * 4 + 2) * 68 + lrow] = q4.z * qscale;
        Qt[(dbase + u * 4 + 3) * 68 + lrow] = q4.w * qscale;
    }

    float m_run[8], l_run[8], o[8][4];
#pragma unroll
    for (int i = 0; i < 8; i++) {
        m_run[i] = -INFINITY;
        l_run[i] = 0.f;
#pragma unroll
        for (int j = 0; j < 4; j++) o[i][j] = 0.f;
    }

    for (int kt = 0; kt < NKV; kt += 64) {
        __syncthreads();
#pragma unroll
        for (int u = 0; u < 8; u++) {
            float4 k4 = *(const float4*)&Kp[(size_t)(kt + lrow) * HD + dbase + u * 4];
            Kt[(dbase + u * 4 + 0) * 68 + lrow] = k4.x;
            Kt[(dbase + u * 4 + 1) * 68 + lrow] = k4.y;
            Kt[(dbase + u * 4 + 2) * 68 + lrow] = k4.z;
            Kt[(dbase + u * 4 + 3) * 68 + lrow] = k4.w;
            float4 v4 = *(const float4*)&Vp[(size_t)(kt + lrow) * HD + dbase + u * 4];
            *(float4*)&Vs[lrow * 68 + dbase + u * 4] = v4;
        }
        __syncthreads();

        // S = Q K^T (log2-scaled)
        float s[8][4];
#pragma unroll
        for (int i = 0; i < 8; i++)
#pragma unroll
            for (int j = 0; j < 4; j++) s[i][j] = 0.f;
#pragma unroll 8
        for (int d = 0; d < 64; d++) {
            float4 a0  = *(const float4*)&Qt[d * 68 + ty * 8];
            float4 a1  = *(const float4*)&Qt[d * 68 + ty * 8 + 4];
            float4 kv4 = *(const float4*)&Kt[d * 68 + tx * 4];
            float a[8]  = {a0.x, a0.y, a0.z, a0.w, a1.x, a1.y, a1.z, a1.w};
            float kb[4] = {kv4.x, kv4.y, kv4.z, kv4.w};
#pragma unroll
            for (int i = 0; i < 8; i++)
#pragma unroll
                for (int j = 0; j < 4; j++) s[i][j] += a[i] * kb[j];
        }

        // online softmax (base 2); row spread over 16 tx lanes
#pragma unroll
        for (int i = 0; i < 8; i++) {
            float mx = fmaxf(fmaxf(s[i][0], s[i][1]), fmaxf(s[i][2], s[i][3]));
#pragma unroll
            for (int off = 8; off > 0; off >>= 1)
                mx = fmaxf(mx, __shfl_xor_sync(0xffffffffu, mx, off));
            const float mnew = fmaxf(m_run[i], mx);
            const float corr = ex2(m_run[i] - mnew);
            float rs = 0.f;
#pragma unroll
            for (int j = 0; j < 4; j++) {
                const float pv = ex2(s[i][j] - mnew);
                s[i][j] = pv;
                rs += pv;
            }
#pragma unroll
            for (int off = 8; off > 0; off >>= 1)
                rs += __shfl_xor_sync(0xffffffffu, rs, off);
            l_run[i] = l_run[i] * corr + rs;
            m_run[i] = mnew;
#pragma unroll
            for (int j = 0; j < 4; j++) o[i][j] *= corr;
#pragma unroll
            for (int j = 0; j < 4; j++)
                Ss[(tx * 4 + j) * 68 + ty * 8 + i] = s[i][j];
        }
        __syncthreads();

        // O += P V  (P transposed in smem -> vector loads)
#pragma unroll 8
        for (int kk = 0; kk < 64; kk++) {
            float4 p0 = *(const float4*)&Ss[kk * 68 + ty * 8];
            float4 p1 = *(const float4*)&Ss[kk * 68 + ty * 8 + 4];
            float4 v4 = *(const float4*)&Vs[kk * 68 + tx * 4];
            float p[8]  = {p0.x, p0.y, p0.z, p0.w, p1.x, p1.y, p1.z, p1.w};
            float vv[4] = {v4.x, v4.y, v4.z, v4.w};
#pragma unroll
            for (int i = 0; i < 8; i++)
#pragma unroll
                for (int j = 0; j < 4; j++) o[i][j] += p[i] * vv[j];
        }
    }

#pragma unroll
    for (int i = 0; i < 8; i++) {
        const float inv  = 1.f / l_run[i];
        const int   qrow = qt * 64 + ty * 8 + i;
        float4 ov = make_float4(o[i][0] * inv, o[i][1] * inv,
                                o[i][2] * inv, o[i][3] * inv);
        *(float4*)&Out[((size_t)b * NQ + qrow) * CD + h * HD + tx * 4] = ov;
    }
}

// ---------------------------------------------------------------------------
extern "C" void kernel_launch(void* const* d_in, const int* in_sizes, int n_in,
                              void* d_out, int out_size)
{
    const float* x    = (const float*)d_in[0];
    const float* Wq   = (const float*)d_in[1];
    const float* bq   = (const float*)d_in[2];
    const float* Wk   = (const float*)d_in[3];
    const float* bk   = (const float*)d_in[4];
    const float* Wv   = (const float*)d_in[5];
    const float* bv   = (const float*)d_in[6];
    const float* Wp   = (const float*)d_in[7];
    const float* bp   = (const float*)d_in[8];
    const float* sr_w = (const float*)d_in[9];
    const float* sr_b = (const float*)d_in[10];
    const float* ln_g = (const float*)d_in[11];
    const float* ln_b = (const float*)d_in[12];
    float* out = (float*)d_out;

    float *kv, *qb, *kb, *vb, *ab;
    cudaGetSymbolAddress((void**)&kv, g_kv);
    cudaGetSymbolAddress((void**)&qb, g_q);
    cudaGetSymbolAddress((void**)&kb, g_k);
    cudaGetSymbolAddress((void**)&vb, g_v);
    cudaGetSymbolAddress((void**)&ab, g_attn);

    // 1. SR conv (patch GEMM) -> kv_raw
    conv_gemm<<<dim3(4, 64), 256>>>(x, sr_w, sr_b, kv);
    // 2. LayerNorm in place
    ln_kernel<<<BQ * NKV, 256>>>(kv, ln_g, ln_b);
    // 3. Q projection (head-major scatter), fused K+V projection
    gemm_tile<8, 1, 12><<<dim3(4, 128), 256>>>(x,  Wq, Wq, bq, bq, qb, qb, 512);
    gemm_tile<4, 2, 10><<<dim3(8, 64),  256>>>(kv, Wk, Wv, bk, bv, kb, vb, 512);
    // 4. flash attention
    const int fl_smem = FTOT * (int)sizeof(float);
    cudaFuncSetAttribute(flash_kernel,
                         cudaFuncAttributeMaxDynamicSharedMemorySize, fl_smem);
    flash_kernel<<<dim3(NQ / 64, NH, BQ), 128, fl_smem>>>(qb, kb, vb, ab);
    // 5. output projection
    gemm_tile<8, 0, 1><<<dim3(4, 128), 256>>>(ab, Wp, Wp, bp, bp, out, out, 512);
}

// round 9
// speedup vs baseline: 1.0552x; 1.0552x over previous
#include <cuda_runtime.h>
#include <math.h>

// Problem constants
#define BQ   4
#define NQ   4096
#define NKV  1024
#define CD   512
#define NH   8
#define HD   64

// Scratch (device globals: allocation-free rule)
__device__ float g_kv  [BQ * NKV * CD];        // 2M  floats
__device__ float g_q   [BQ * NH * NQ  * HD];   // 8M  floats, [b][h][n][d]
__device__ float g_k   [BQ * NH * NKV * HD];   // 2M  floats
__device__ float g_v   [BQ * NH * NKV * HD];   // 2M  floats
__device__ float g_attn[BQ * NQ * CD];         // 8M  floats, [b][n][h*64+d]

__device__ __forceinline__ float ex2(float x) {
    float r;
    asm("ex2.approx.f32 %0, %1;" : "=f"(r) : "f"(x));
    return r;
}

// ---------------------------------------------------------------------------
// Tiled GEMM: BM = TM*16 x 128 tile, 256 threads, per-thread TM x 8.
// N (row stride of B / C) fixed at 512.
// MODE 0: row-major store (C0). MODE 1: head-major scatter (C0).
// MODE 2: dual weights/outputs (B0/C0 for n<512, B1/C1 for n>=512), scatter.
// NB: log2(rows per batch) for the scatter decode.
// ---------------------------------------------------------------------------
template <int TM, int MODE, int NB>
__global__ __launch_bounds__(256)
void gemm_tile(const float* __restrict__ A,
               const float* __restrict__ B0, const float* __restrict__ B1,
               const float* __restrict__ bias0, const float* __restrict__ bias1,
               float* __restrict__ C0, float* __restrict__ C1, int K)
{
    constexpr int BM = TM * 16;
    __shared__ float As[16][BM + 4];   // [k][m] transposed, padded
    __shared__ float Bs[16][128];      // [k][n]

    const int m0 = blockIdx.y * BM;
    const int n0 = blockIdx.x * 128;

    const bool second = (MODE == 2) && (n0 >= 512);
    const float* Bm   = second ? B1 : B0;
    const float* bias = second ? bias1 : bias0;
    float*       Cout = second ? C1 : C0;
    const int    n0l  = second ? (n0 - 512) : n0;

    const int t  = threadIdx.x;
    const int tx = t & 15;
    const int ty = t >> 4;
    const int brow = t >> 4;
    const int bcol = (t & 15) * 8;

    int arow, ak;
    if (TM == 8) { arow = t >> 1; ak = (t & 1) * 8; }
    else         { arow = t >> 2; ak = (t & 3) * 4; }
    const float* Ap = A + (size_t)(m0 + arow) * K;

    float acc[TM][8];
#pragma unroll
    for (int i = 0; i < TM; i++)
#pragma unroll
        for (int j = 0; j < 8; j++) acc[i][j] = 0.f;

    for (int k0 = 0; k0 < K; k0 += 16) {
        if (TM == 8) {
            float4 a0 = *(const float4*)(Ap + k0 + ak);
            float4 a1 = *(const float4*)(Ap + k0 + ak + 4);
            As[ak + 0][arow] = a0.x; As[ak + 1][arow] = a0.y;
            As[ak + 2][arow] = a0.z; As[ak + 3][arow] = a0.w;
            As[ak + 4][arow] = a1.x; As[ak + 5][arow] = a1.y;
            As[ak + 6][arow] = a1.z; As[ak + 7][arow] = a1.w;
        } else {
            float4 a0 = *(const float4*)(Ap + k0 + ak);
            As[ak + 0][arow] = a0.x; As[ak + 1][arow] = a0.y;
            As[ak + 2][arow] = a0.z; As[ak + 3][arow] = a0.w;
        }
        const float* Brow = Bm + (size_t)(k0 + brow) * 512 + n0l + bcol;
        *(float4*)&Bs[brow][bcol]     = *(const float4*)Brow;
        *(float4*)&Bs[brow][bcol + 4] = *(const float4*)(Brow + 4);
        __syncthreads();

#pragma unroll
        for (int kk = 0; kk < 16; kk++) {
            float a[TM];
#pragma unroll
            for (int v = 0; v < TM / 4; v++) {
                float4 av = *(const float4*)&As[kk][ty * TM + v * 4];
                a[v * 4 + 0] = av.x; a[v * 4 + 1] = av.y;
                a[v * 4 + 2] = av.z; a[v * 4 + 3] = av.w;
            }
            float4 b0 = *(const float4*)&Bs[kk][tx * 8];
            float4 b1 = *(const float4*)&Bs[kk][tx * 8 + 4];
            float bb[8] = {b0.x, b0.y, b0.z, b0.w, b1.x, b1.y, b1.z, b1.w};
#pragma unroll
            for (int i = 0; i < TM; i++)
#pragma unroll
                for (int j = 0; j < 8; j++) acc[i][j] += a[i] * bb[j];
        }
        __syncthreads();
    }

    float bias_r[8];
    {
        float4 c0 = *(const float4*)&bias[n0l + tx * 8];
        float4 c1 = *(const float4*)&bias[n0l + tx * 8 + 4];
        bias_r[0] = c0.x; bias_r[1] = c0.y; bias_r[2] = c0.z; bias_r[3] = c0.w;
        bias_r[4] = c1.x; bias_r[5] = c1.y; bias_r[6] = c1.z; bias_r[7] = c1.w;
    }

    if (MODE == 0) {
#pragma unroll
        for (int i = 0; i < TM; i++) {
            const int m = m0 + ty * TM + i;
            float4 o0 = make_float4(acc[i][0] + bias_r[0], acc[i][1] + bias_r[1],
                                    acc[i][2] + bias_r[2], acc[i][3] + bias_r[3]);
            float4 o1 = make_float4(acc[i][4] + bias_r[4], acc[i][5] + bias_r[5],
                                    acc[i][6] + bias_r[6], acc[i][7] + bias_r[7]);
            *(float4*)&Cout[(size_t)m * 512 + n0l + tx * 8]     = o0;
            *(float4*)&Cout[(size_t)m * 512 + n0l + tx * 8 + 4] = o1;
        }
    } else {
        // head-major scatter: c = n0l + tx*8 + j, h = j (since base div by 8), d fixed
        const int d0 = (n0l + tx * 8) >> 3;
#pragma unroll
        for (int i = 0; i < TM; i++) {
            const int m  = m0 + ty * TM + i;
            const int bb2 = m >> NB;
            const int nn  = m & ((1 << NB) - 1);
#pragma unroll
            for (int j = 0; j < 8; j++) {
                Cout[((((size_t)(bb2 * NH + j)) << NB) + nn) * HD + d0] =
                    acc[i][j] + bias_r[j];
            }
        }
    }
}

// ---------------------------------------------------------------------------
// SR conv as GEMM with gathered A: M=4096 (b,i,j), K=2048 (di,dj,c), N=512.
// 64x128 tile, 4x8 per thread.
// ---------------------------------------------------------------------------
__global__ __launch_bounds__(256)
void conv_gemm(const float* __restrict__ x,
               const float* __restrict__ Wm,
               const float* __restrict__ bias,
               float* __restrict__ Cout)
{
    __shared__ float As[16][68];
    __shared__ float Bs[16][128];

    const int m0 = blockIdx.y * 64;
    const int n0 = blockIdx.x * 128;
    const int t  = threadIdx.x;
    const int tx = t & 15;
    const int ty = t >> 4;
    const int arow = t >> 2;
    const int ak   = (t & 3) * 4;
    const int brow = t >> 4;
    const int bcol = (t & 15) * 8;

    const int m   = m0 + arow;
    const int b   = m >> 10;
    const int rem = m & 1023;
    const int ii  = rem >> 5;
    const int jj  = rem & 31;

    float acc[4][8];
#pragma unroll
    for (int i = 0; i < 4; i++)
#pragma unroll
        for (int j = 0; j < 8; j++) acc[i][j] = 0.f;

    for (int k0 = 0; k0 < 2048; k0 += 16) {
        const int k   = k0 + ak;
        const int blk = k >> 9;
        const int c   = k & 511;
        const int di  = blk >> 1;
        const int dj  = blk & 1;
        float4 a0 = *(const float4*)&x[
            (size_t)((b * 64 + 2 * ii + di) * 64 + (2 * jj + dj)) * 512 + c];
        As[ak + 0][arow] = a0.x; As[ak + 1][arow] = a0.y;
        As[ak + 2][arow] = a0.z; As[ak + 3][arow] = a0.w;
        const float* Brow = Wm + (size_t)(k0 + brow) * 512 + n0 + bcol;
        *(float4*)&Bs[brow][bcol]     = *(const float4*)Brow;
        *(float4*)&Bs[brow][bcol + 4] = *(const float4*)(Brow + 4);
        __syncthreads();

#pragma unroll
        for (int kk = 0; kk < 16; kk++) {
            float4 av = *(const float4*)&As[kk][ty * 4];
            float4 b0 = *(const float4*)&Bs[kk][tx * 8];
            float4 b1 = *(const float4*)&Bs[kk][tx * 8 + 4];
            float a[4]  = {av.x, av.y, av.z, av.w};
            float bb[8] = {b0.x, b0.y, b0.z, b0.w, b1.x, b1.y, b1.z, b1.w};
#pragma unroll
            for (int i = 0; i < 4; i++)
#pragma unroll
                for (int j = 0; j < 8; j++) acc[i][j] += a[i] * bb[j];
        }
        __syncthreads();
    }

#pragma unroll
    for (int i = 0; i < 4; i++) {
        const int mm = m0 + ty * 4 + i;
        float4 o0 = make_float4(acc[i][0] + bias[n0 + tx * 8 + 0],
                                acc[i][1] + bias[n0 + tx * 8 + 1],
                                acc[i][2] + bias[n0 + tx * 8 + 2],
                                acc[i][3] + bias[n0 + tx * 8 + 3]);
        float4 o1 = make_float4(acc[i][4] + bias[n0 + tx * 8 + 4],
                                acc[i][5] + bias[n0 + tx * 8 + 5],
                                acc[i][6] + bias[n0 + tx * 8 + 6],
                                acc[i][7] + bias[n0 + tx * 8 + 7]);
        *(float4*)&Cout[(size_t)mm * 512 + n0 + tx * 8]     = o0;
        *(float4*)&Cout[(size_t)mm * 512 + n0 + tx * 8 + 4] = o1;
    }
}

// ---------------------------------------------------------------------------
// LayerNorm in-place over the last dim (512) of g_kv. One block per row.
// ---------------------------------------------------------------------------
__global__ void ln_kernel(float* __restrict__ kv,
                          const float* __restrict__ gam,
                          const float* __restrict__ bet)
{
    __shared__ float red[256];
    const int row = blockIdx.x;
    const int t   = threadIdx.x;
    float* p = kv + (size_t)row * 512;

    float v0 = p[t], v1 = p[t + 256];
    red[t] = v0 + v1;
    __syncthreads();
    for (int o = 128; o > 0; o >>= 1) {
        if (t < o) red[t] += red[t + o];
        __syncthreads();
    }
    const float mu = red[0] * (1.f / 512.f);
    __syncthreads();

    const float d0 = v0 - mu, d1 = v1 - mu;
    red[t] = d0 * d0 + d1 * d1;
    __syncthreads();
    for (int o = 128; o > 0; o >>= 1) {
        if (t < o) red[t] += red[t + o];
        __syncthreads();
    }
    const float var = red[0] * (1.f / 512.f);
    const float r   = rsqrtf(var + 1e-6f);
    p[t]       = d0 * r * gam[t]       + bet[t];
    p[t + 256] = d1 * r * gam[t + 256] + bet[t + 256];
}

// ---------------------------------------------------------------------------
// Flash attention: one block per (b, h, 64-q tile). 128 threads, 8x4/thread.
// Qt/Kt transposed [d][n]; P stored transposed [k][q] for vector PV loads.
// Base-2 softmax: Q pre-scaled by 0.125*log2(e), exp via ex2.approx.
// ---------------------------------------------------------------------------
#define FQT 0          // Qt[64][68]
#define FKT 4352       // Kt[64][68]
#define FSS 8704       // Ss[64][68] transposed [k][q]
#define FVS 13056      // Vs[64][68]
#define FTOT 17408

__global__ __launch_bounds__(128)
void flash_kernel(const float* __restrict__ Q,
                  const float* __restrict__ Kk,
                  const float* __restrict__ V,
                  float* __restrict__ Out)
{
    extern __shared__ float sm[];
    float* Qt = sm + FQT;
    float* Kt = sm + FKT;
    float* Ss = sm + FSS;
    float* Vs = sm + FVS;

    const int b  = blockIdx.z;
    const int h  = blockIdx.y;
    const int qt = blockIdx.x;

    const float* Qp = Q  + ((size_t)(b * NH + h) * NQ + qt * 64) * HD;
    const float* Kp = Kk + (size_t)(b * NH + h) * NKV * HD;
    const float* Vp = V  + (size_t)(b * NH + h) * NKV * HD;

    const int t     = threadIdx.x;
    const int tx    = t & 15;
    const int ty    = t >> 4;          // 0..7
    const int lrow  = t >> 1;          // 0..63
    const int dbase = (t & 1) * 32;

    const float qscale = 0.125f * 1.44269504088896340736f;

#pragma unroll
    for (int u = 0; u < 8; u++) {
        float4 q4 = *(const float4*)&Qp[(size_t)lrow * HD + dbase + u * 4];
        Qt[(dbase + u * 4 + 0) * 68 + lrow] = q4.x * qscale;
        Qt[(dbase + u * 4 + 1) * 68 + lrow] = q4.y * qscale;
        Qt[(dbase + u * 4 + 2) * 68 + lrow] = q4.z * qscale;
        Qt[(dbase + u * 4 + 3) * 68 + lrow] = q4.w * qscale;
    }

    float m_run[8], l_run[8], o[8][4];
#pragma unroll
    for (int i = 0; i < 8; i++) {
        m_run[i] = -INFINITY;
        l_run[i] = 0.f;
#pragma unroll
        for (int j = 0; j < 4; j++) o[i][j] = 0.f;
    }

    for (int kt = 0; kt < NKV; kt += 64) {
        __syncthreads();
#pragma unroll
        for (int u = 0; u < 8; u++) {
            float4 k4 = *(const float4*)&Kp[(size_t)(kt + lrow) * HD + dbase + u * 4];
            Kt[(dbase + u * 4 + 0) * 68 + lrow] = k4.x;
            Kt[(dbase + u * 4 + 1) * 68 + lrow] = k4.y;
            Kt[(dbase + u * 4 + 2) * 68 + lrow] = k4.z;
            Kt[(dbase + u * 4 + 3) * 68 + lrow] = k4.w;
            float4 v4 = *(const float4*)&Vp[(size_t)(kt + lrow) * HD + dbase + u * 4];
            *(float4*)&Vs[lrow * 68 + dbase + u * 4] = v4;
        }
        __syncthreads();

        // S = Q K^T (log2-scaled)
        float s[8][4];
#pragma unroll
        for (int i = 0; i < 8; i++)
#pragma unroll
            for (int j = 0; j < 4; j++) s[i][j] = 0.f;
#pragma unroll 8
        for (int d = 0; d < 64; d++) {
            float4 a0  = *(const float4*)&Qt[d * 68 + ty * 8];
            float4 a1  = *(const float4*)&Qt[d * 68 + ty * 8 + 4];
            float4 kv4 = *(const float4*)&Kt[d * 68 + tx * 4];
            float a[8]  = {a0.x, a0.y, a0.z, a0.w, a1.x, a1.y, a1.z, a1.w};
            float kb[4] = {kv4.x, kv4.y, kv4.z, kv4.w};
#pragma unroll
            for (int i = 0; i < 8; i++)
#pragma unroll
                for (int j = 0; j < 4; j++) s[i][j] += a[i] * kb[j];
        }

        // online softmax (base 2); row spread over 16 tx lanes
#pragma unroll
        for (int i = 0; i < 8; i++) {
            float mx = fmaxf(fmaxf(s[i][0], s[i][1]), fmaxf(s[i][2], s[i][3]));
#pragma unroll
            for (int off = 8; off > 0; off >>= 1)
                mx = fmaxf(mx, __shfl_xor_sync(0xffffffffu, mx, off));
            const float mnew = fmaxf(m_run[i], mx);
            const float corr = ex2(m_run[i] - mnew);
            float rs = 0.f;
#pragma unroll
            for (int j = 0; j < 4; j++) {
                const float pv = ex2(s[i][j] - mnew);
                s[i][j] = pv;
                rs += pv;
            }
#pragma unroll
            for (int off = 8; off > 0; off >>= 1)
                rs += __shfl_xor_sync(0xffffffffu, rs, off);
            l_run[i] = l_run[i] * corr + rs;
            m_run[i] = mnew;
#pragma unroll
            for (int j = 0; j < 4; j++) o[i][j] *= corr;
#pragma unroll
            for (int j = 0; j < 4; j++)
                Ss[(tx * 4 + j) * 68 + ty * 8 + i] = s[i][j];
        }
        __syncthreads();

        // O += P V  (P transposed in smem -> vector loads)
#pragma unroll 8
        for (int kk = 0; kk < 64; kk++) {
            float4 p0 = *(const float4*)&Ss[kk * 68 + ty * 8];
            float4 p1 = *(const float4*)&Ss[kk * 68 + ty * 8 + 4];
            float4 v4 = *(const float4*)&Vs[kk * 68 + tx * 4];
            float p[8]  = {p0.x, p0.y, p0.z, p0.w, p1.x, p1.y, p1.z, p1.w};
            float vv[4] = {v4.x, v4.y, v4.z, v4.w};
#pragma unroll
            for (int i = 0; i < 8; i++)
#pragma unroll
                for (int j = 0; j < 4; j++) o[i][j] += p[i] * vv[j];
        }
    }

#pragma unroll
    for (int i = 0; i < 8; i++) {
        const float inv  = 1.f / l_run[i];
        const int   qrow = qt * 64 + ty * 8 + i;
        float4 ov = make_float4(o[i][0] * inv, o[i][1] * inv,
                                o[i][2] * inv, o[i][3] * inv);
        *(float4*)&Out[((size_t)b * NQ + qrow) * CD + h * HD + tx * 4] = ov;
    }
}

// ---------------------------------------------------------------------------
extern "C" void kernel_launch(void* const* d_in, const int* in_sizes, int n_in,
                              void* d_out, int out_size)
{
    const float* x    = (const float*)d_in[0];
    const float* Wq   = (const float*)d_in[1];
    const float* bq   = (const float*)d_in[2];
    const float* Wk   = (const float*)d_in[3];
    const float* bk   = (const float*)d_in[4];
    const float* Wv   = (const float*)d_in[5];
    const float* bv   = (const float*)d_in[6];
    const float* Wp   = (const float*)d_in[7];
    const float* bp   = (const float*)d_in[8];
    const float* sr_w = (const float*)d_in[9];
    const float* sr_b = (const float*)d_in[10];
    const float* ln_g = (const float*)d_in[11];
    const float* ln_b = (const float*)d_in[12];
    float* out = (float*)d_out;

    float *kv, *qb, *kb, *vb, *ab;
    cudaGetSymbolAddress((void**)&kv, g_kv);
    cudaGetSymbolAddress((void**)&qb, g_q);
    cudaGetSymbolAddress((void**)&kb, g_k);
    cudaGetSymbolAddress((void**)&vb, g_v);
    cudaGetSymbolAddress((void**)&ab, g_attn);

    // 1. SR conv (patch GEMM) -> kv_raw
    conv_gemm<<<dim3(4, 64), 256>>>(x, sr_w, sr_b, kv);
    // 2. LayerNorm in place
    ln_kernel<<<BQ * NKV, 256>>>(kv, ln_g, ln_b);
    // 3. Q projection (head-major scatter), fused K+V projection
    gemm_tile<8, 1, 12><<<dim3(4, 128), 256>>>(x,  Wq, Wq, bq, bq, qb, qb, 512);
    gemm_tile<4, 2, 10><<<dim3(8, 64),  256>>>(kv, Wk, Wv, bk, bv, kb, vb, 512);
    // 4. flash attention
    const int fl_smem = FTOT * (int)sizeof(float);
    cudaFuncSetAttribute(flash_kernel,
                         cudaFuncAttributeMaxDynamicSharedMemorySize, fl_smem);
    flash_kernel<<<dim3(NQ / 64, NH, BQ), 128, fl_smem>>>(qb, kb, vb, ab);
    // 5. output projection
    gemm_tile<8, 0, 1><<<dim3(4, 128), 256>>>(ab, Wp, Wp, bp, bp, out, out, 512);
}

// round 10
// speedup vs baseline: 1.0565x; 1.0013x over previous
#include <cuda_runtime.h>
#include <math.h>

// Problem constants
#define BQ   4
#define NQ   4096
#define NKV  1024
#define CD   512
#define NH   8
#define HD   64

// Scratch (device globals: allocation-free rule)
__device__ float g_kv  [BQ * NKV * CD];        // 2M  floats
__device__ float g_q   [BQ * NH * NQ  * HD];   // 8M  floats, [b][h][n][d]
__device__ float g_k   [BQ * NH * NKV * HD];   // 2M  floats
__device__ float g_v   [BQ * NH * NKV * HD];   // 2M  floats
__device__ float g_attn[BQ * NQ * CD];         // 8M  floats, [b][n][h*64+d]

__device__ __forceinline__ float ex2(float x) {
    float r;
    asm("ex2.approx.f32 %0, %1;" : "=f"(r) : "f"(x));
    return r;
}

// ---------------------------------------------------------------------------
// Tiled GEMM: BM = TM*16 x 128 tile, 256 threads, per-thread TM x 8.
// N (row stride of B / C) fixed at 512.
// MODE 0: row-major store (C0). MODE 1: head-major scatter (C0).
// MODE 2: dual weights/outputs (B0/C0 for n<512, B1/C1 for n>=512), scatter.
// NB: log2(rows per batch) for the scatter decode.
// ---------------------------------------------------------------------------
template <int TM, int MODE, int NB>
__global__ __launch_bounds__(256)
void gemm_tile(const float* __restrict__ A,
               const float* __restrict__ B0, const float* __restrict__ B1,
               const float* __restrict__ bias0, const float* __restrict__ bias1,
               float* __restrict__ C0, float* __restrict__ C1, int K)
{
    constexpr int BM = TM * 16;
    __shared__ float As[16][BM + 4];   // [k][m] transposed, padded
    __shared__ float Bs[16][128];      // [k][n]

    const int m0 = blockIdx.y * BM;
    const int n0 = blockIdx.x * 128;

    const bool second = (MODE == 2) && (n0 >= 512);
    const float* Bm   = second ? B1 : B0;
    const float* bias = second ? bias1 : bias0;
    float*       Cout = second ? C1 : C0;
    const int    n0l  = second ? (n0 - 512) : n0;

    const int t  = threadIdx.x;
    const int tx = t & 15;
    const int ty = t >> 4;
    const int brow = t >> 4;
    const int bcol = (t & 15) * 8;

    int arow, ak;
    if (TM == 8) { arow = t >> 1; ak = (t & 1) * 8; }
    else         { arow = t >> 2; ak = (t & 3) * 4; }
    const float* Ap = A + (size_t)(m0 + arow) * K;

    float acc[TM][8];
#pragma unroll
    for (int i = 0; i < TM; i++)
#pragma unroll
        for (int j = 0; j < 8; j++) acc[i][j] = 0.f;

    for (int k0 = 0; k0 < K; k0 += 16) {
        if (TM == 8) {
            float4 a0 = *(const float4*)(Ap + k0 + ak);
            float4 a1 = *(const float4*)(Ap + k0 + ak + 4);
            As[ak + 0][arow] = a0.x; As[ak + 1][arow] = a0.y;
            As[ak + 2][arow] = a0.z; As[ak + 3][arow] = a0.w;
            As[ak + 4][arow] = a1.x; As[ak + 5][arow] = a1.y;
            As[ak + 6][arow] = a1.z; As[ak + 7][arow] = a1.w;
        } else {
            float4 a0 = *(const float4*)(Ap + k0 + ak);
            As[ak + 0][arow] = a0.x; As[ak + 1][arow] = a0.y;
            As[ak + 2][arow] = a0.z; As[ak + 3][arow] = a0.w;
        }
        const float* Brow = Bm + (size_t)(k0 + brow) * 512 + n0l + bcol;
        *(float4*)&Bs[brow][bcol]     = *(const float4*)Brow;
        *(float4*)&Bs[brow][bcol + 4] = *(const float4*)(Brow + 4);
        __syncthreads();

#pragma unroll
        for (int kk = 0; kk < 16; kk++) {
            float a[TM];
#pragma unroll
            for (int v = 0; v < TM / 4; v++) {
                float4 av = *(const float4*)&As[kk][ty * TM + v * 4];
                a[v * 4 + 0] = av.x; a[v * 4 + 1] = av.y;
                a[v * 4 + 2] = av.z; a[v * 4 + 3] = av.w;
            }
            float4 b0 = *(const float4*)&Bs[kk][tx * 8];
            float4 b1 = *(const float4*)&Bs[kk][tx * 8 + 4];
            float bb[8] = {b0.x, b0.y, b0.z, b0.w, b1.x, b1.y, b1.z, b1.w};
#pragma unroll
            for (int i = 0; i < TM; i++)
#pragma unroll
                for (int j = 0; j < 8; j++) acc[i][j] += a[i] * bb[j];
        }
        __syncthreads();
    }

    float bias_r[8];
    {
        float4 c0 = *(const float4*)&bias[n0l + tx * 8];
        float4 c1 = *(const float4*)&bias[n0l + tx * 8 + 4];
        bias_r[0] = c0.x; bias_r[1] = c0.y; bias_r[2] = c0.z; bias_r[3] = c0.w;
        bias_r[4] = c1.x; bias_r[5] = c1.y; bias_r[6] = c1.z; bias_r[7] = c1.w;
    }

    if (MODE == 0) {
#pragma unroll
        for (int i = 0; i < TM; i++) {
            const int m = m0 + ty * TM + i;
            float4 o0 = make_float4(acc[i][0] + bias_r[0], acc[i][1] + bias_r[1],
                                    acc[i][2] + bias_r[2], acc[i][3] + bias_r[3]);
            float4 o1 = make_float4(acc[i][4] + bias_r[4], acc[i][5] + bias_r[5],
                                    acc[i][6] + bias_r[6], acc[i][7] + bias_r[7]);
            *(float4*)&Cout[(size_t)m * 512 + n0l + tx * 8]     = o0;
            *(float4*)&Cout[(size_t)m * 512 + n0l + tx * 8 + 4] = o1;
        }
    } else {
        // head-major scatter: c = n0l + tx*8 + j, h = j (since base div by 8), d fixed
        const int d0 = (n0l + tx * 8) >> 3;
#pragma unroll
        for (int i = 0; i < TM; i++) {
            const int m  = m0 + ty * TM + i;
            const int bb2 = m >> NB;
            const int nn  = m & ((1 << NB) - 1);
#pragma unroll
            for (int j = 0; j < 8; j++) {
                Cout[((((size_t)(bb2 * NH + j)) << NB) + nn) * HD + d0] =
                    acc[i][j] + bias_r[j];
            }
        }
    }
}

// ---------------------------------------------------------------------------
// SR conv as GEMM with gathered A: M=4096 (b,i,j), K=2048 (di,dj,c), N=512.
// 64x128 tile, 4x8 per thread.
// ---------------------------------------------------------------------------
__global__ __launch_bounds__(256)
void conv_gemm(const float* __restrict__ x,
               const float* __restrict__ Wm,
               const float* __restrict__ bias,
               float* __restrict__ Cout)
{
    __shared__ float As[16][68];
    __shared__ float Bs[16][128];

    const int m0 = blockIdx.y * 64;
    const int n0 = blockIdx.x * 128;
    const int t  = threadIdx.x;
    const int tx = t & 15;
    const int ty = t >> 4;
    const int arow = t >> 2;
    const int ak   = (t & 3) * 4;
    const int brow = t >> 4;
    const int bcol = (t & 15) * 8;

    const int m   = m0 + arow;
    const int b   = m >> 10;
    const int rem = m & 1023;
    const int ii  = rem >> 5;
    const int jj  = rem & 31;

    float acc[4][8];
#pragma unroll
    for (int i = 0; i < 4; i++)
#pragma unroll
        for (int j = 0; j < 8; j++) acc[i][j] = 0.f;

    for (int k0 = 0; k0 < 2048; k0 += 16) {
        const int k   = k0 + ak;
        const int blk = k >> 9;
        const int c   = k & 511;
        const int di  = blk >> 1;
        const int dj  = blk & 1;
        float4 a0 = *(const float4*)&x[
            (size_t)((b * 64 + 2 * ii + di) * 64 + (2 * jj + dj)) * 512 + c];
        As[ak + 0][arow] = a0.x; As[ak + 1][arow] = a0.y;
        As[ak + 2][arow] = a0.z; As[ak + 3][arow] = a0.w;
        const float* Brow = Wm + (size_t)(k0 + brow) * 512 + n0 + bcol;
        *(float4*)&Bs[brow][bcol]     = *(const float4*)Brow;
        *(float4*)&Bs[brow][bcol + 4] = *(const float4*)(Brow + 4);
        __syncthreads();

#pragma unroll
        for (int kk = 0; kk < 16; kk++) {
            float4 av = *(const float4*)&As[kk][ty * 4];
            float4 b0 = *(const float4*)&Bs[kk][tx * 8];
            float4 b1 = *(const float4*)&Bs[kk][tx * 8 + 4];
            float a[4]  = {av.x, av.y, av.z, av.w};
            float bb[8] = {b0.x, b0.y, b0.z, b0.w, b1.x, b1.y, b1.z, b1.w};
#pragma unroll
            for (int i = 0; i < 4; i++)
#pragma unroll
                for (int j = 0; j < 8; j++) acc[i][j] += a[i] * bb[j];
        }
        __syncthreads();
    }

#pragma unroll
    for (int i = 0; i < 4; i++) {
        const int mm = m0 + ty * 4 + i;
        float4 o0 = make_float4(acc[i][0] + bias[n0 + tx * 8 + 0],
                                acc[i][1] + bias[n0 + tx * 8 + 1],
                                acc[i][2] + bias[n0 + tx * 8 + 2],
                                acc[i][3] + bias[n0 + tx * 8 + 3]);
        float4 o1 = make_float4(acc[i][4] + bias[n0 + tx * 8 + 4],
                                acc[i][5] + bias[n0 + tx * 8 + 5],
                                acc[i][6] + bias[n0 + tx * 8 + 6],
                                acc[i][7] + bias[n0 + tx * 8 + 7]);
        *(float4*)&Cout[(size_t)mm * 512 + n0 + tx * 8]     = o0;
        *(float4*)&Cout[(size_t)mm * 512 + n0 + tx * 8 + 4] = o1;
    }
}

// ---------------------------------------------------------------------------
// LayerNorm in-place over the last dim (512) of g_kv. One block per row.
// ---------------------------------------------------------------------------
__global__ void ln_kernel(float* __restrict__ kv,
                          const float* __restrict__ gam,
                          const float* __restrict__ bet)
{
    __shared__ float red[256];
    const int row = blockIdx.x;
    const int t   = threadIdx.x;
    float* p = kv + (size_t)row * 512;

    float v0 = p[t], v1 = p[t + 256];
    red[t] = v0 + v1;
    __syncthreads();
    for (int o = 128; o > 0; o >>= 1) {
        if (t < o) red[t] += red[t + o];
        __syncthreads();
    }
    const float mu = red[0] * (1.f / 512.f);
    __syncthreads();

    const float d0 = v0 - mu, d1 = v1 - mu;
    red[t] = d0 * d0 + d1 * d1;
    __syncthreads();
    for (int o = 128; o > 0; o >>= 1) {
        if (t < o) red[t] += red[t + o];
        __syncthreads();
    }
    const float var = red[0] * (1.f / 512.f);
    const float r   = rsqrtf(var + 1e-6f);
    p[t]       = d0 * r * gam[t]       + bet[t];
    p[t + 256] = d1 * r * gam[t + 256] + bet[t + 256];
}

// ---------------------------------------------------------------------------
// Flash attention: one block per (b, h, 64-q tile). 128 threads, 8x4/thread.
// Qt/Kt transposed [d][n]; P stored transposed [k][q] for vector PV loads.
// Base-2 softmax: Q pre-scaled by 0.125*log2(e), exp via ex2.approx.
// ---------------------------------------------------------------------------
#define FQT 0          // Qt[64][68]
#define FKT 4352       // Kt[64][68]
#define FSS 8704       // Ss[64][68] transposed [k][q]
#define FVS 13056      // Vs[64][68]
#define FTOT 17408

__global__ __launch_bounds__(128)
void flash_kernel(const float* __restrict__ Q,
                  const float* __restrict__ Kk,
                  const float* __restrict__ V,
                  float* __restrict__ Out)
{
    extern __shared__ float sm[];
    float* Qt = sm + FQT;
    float* Kt = sm + FKT;
    float* Ss = sm + FSS;
    float* Vs = sm + FVS;

    const int b  = blockIdx.z;
    const int h  = blockIdx.y;
    const int qt = blockIdx.x;

    const float* Qp = Q  + ((size_t)(b * NH + h) * NQ + qt * 64) * HD;
    const float* Kp = Kk + (size_t)(b * NH + h) * NKV * HD;
    const float* Vp = V  + (size_t)(b * NH + h) * NKV * HD;

    const int t     = threadIdx.x;
    const int tx    = t & 15;
    const int ty    = t >> 4;          // 0..7
    const int lrow  = t >> 1;          // 0..63
    const int dbase = (t & 1) * 32;

    const float qscale = 0.125f * 1.44269504088896340736f;

#pragma unroll
    for (int u = 0; u < 8; u++) {
        float4 q4 = *(const float4*)&Qp[(size_t)lrow * HD + dbase + u * 4];
        Qt[(dbase + u * 4 + 0) * 68 + lrow] = q4.x * qscale;
        Qt[(dbase + u * 4 + 1) * 68 + lrow] = q4.y * qscale;
        Qt[(dbase + u * 4 + 2) * 68 + lrow] = q4.z * qscale;
        Qt[(dbase + u * 4 + 3) * 68 + lrow] = q4.w * qscale;
    }

    float m_run[8], l_run[8], o[8][4];
#pragma unroll
    for (int i = 0; i < 8; i++) {
        m_run[i] = -INFINITY;
        l_run[i] = 0.f;
#pragma unroll
        for (int j = 0; j < 4; j++) o[i][j] = 0.f;
    }

    for (int kt = 0; kt < NKV; kt += 64) {
        __syncthreads();
#pragma unroll
        for (int u = 0; u < 8; u++) {
            float4 k4 = *(const float4*)&Kp[(size_t)(kt + lrow) * HD + dbase + u * 4];
            Kt[(dbase + u * 4 + 0) * 68 + lrow] = k4.x;
            Kt[(dbase + u * 4 + 1) * 68 + lrow] = k4.y;
            Kt[(dbase + u * 4 + 2) * 68 + lrow] = k4.z;
            Kt[(dbase + u * 4 + 3) * 68 + lrow] = k4.w;
            float4 v4 = *(const float4*)&Vp[(size_t)(kt + lrow) * HD + dbase + u * 4];
            *(float4*)&Vs[lrow * 68 + dbase + u * 4] = v4;
        }
        __syncthreads();

        // S = Q K^T (log2-scaled)
        float s[8][4];
#pragma unroll
        for (int i = 0; i < 8; i++)
#pragma unroll
            for (int j = 0; j < 4; j++) s[i][j] = 0.f;
#pragma unroll 8
        for (int d = 0; d < 64; d++) {
            float4 a0  = *(const float4*)&Qt[d * 68 + ty * 8];
            float4 a1  = *(const float4*)&Qt[d * 68 + ty * 8 + 4];
            float4 kv4 = *(const float4*)&Kt[d * 68 + tx * 4];
            float a[8]  = {a0.x, a0.y, a0.z, a0.w, a1.x, a1.y, a1.z, a1.w};
            float kb[4] = {kv4.x, kv4.y, kv4.z, kv4.w};
#pragma unroll
            for (int i = 0; i < 8; i++)
#pragma unroll
                for (int j = 0; j < 4; j++) s[i][j] += a[i] * kb[j];
        }

        // online softmax (base 2); row spread over 16 tx lanes
#pragma unroll
        for (int i = 0; i < 8; i++) {
            float mx = fmaxf(fmaxf(s[i][0], s[i][1]), fmaxf(s[i][2], s[i][3]));
#pragma unroll
            for (int off = 8; off > 0; off >>= 1)
                mx = fmaxf(mx, __shfl_xor_sync(0xffffffffu, mx, off));
            const float mnew = fmaxf(m_run[i], mx);
            const float corr = ex2(m_run[i] - mnew);
            float rs = 0.f;
#pragma unroll
            for (int j = 0; j < 4; j++) {
                const float pv = ex2(s[i][j] - mnew);
                s[i][j] = pv;
                rs += pv;
            }
#pragma unroll
            for (int off = 8; off > 0; off >>= 1)
                rs += __shfl_xor_sync(0xffffffffu, rs, off);
            l_run[i] = l_run[i] * corr + rs;
            m_run[i] = mnew;
#pragma unroll
            for (int j = 0; j < 4; j++) o[i][j] *= corr;
#pragma unroll
            for (int j = 0; j < 4; j++)
                Ss[(tx * 4 + j) * 68 + ty * 8 + i] = s[i][j];
        }
        __syncthreads();

        // O += P V  (P transposed in smem -> vector loads)
#pragma unroll 8
        for (int kk = 0; kk < 64; kk++) {
            float4 p0 = *(const float4*)&Ss[kk * 68 + ty * 8];
            float4 p1 = *(const float4*)&Ss[kk * 68 + ty * 8 + 4];
            float4 v4 = *(const float4*)&Vs[kk * 68 + tx * 4];
            float p[8]  = {p0.x, p0.y, p0.z, p0.w, p1.x, p1.y, p1.z, p1.w};
            float vv[4] = {v4.x, v4.y, v4.z, v4.w};
#pragma unroll
            for (int i = 0; i < 8; i++)
#pragma unroll
                for (int j = 0; j < 4; j++) o[i][j] += p[i] * vv[j];
        }
    }

#pragma unroll
    for (int i = 0; i < 8; i++) {
        const float inv  = 1.f / l_run[i];
        const int   qrow = qt * 64 + ty * 8 + i;
        float4 ov = make_float4(o[i][0] * inv, o[i][1] * inv,
                                o[i][2] * inv, o[i][3] * inv);
        *(float4*)&Out[((size_t)b * NQ + qrow) * CD + h * HD + tx * 4] = ov;
    }
}

// ---------------------------------------------------------------------------
extern "C" void kernel_launch(void* const* d_in, const int* in_sizes, int n_in,
                              void* d_out, int out_size)
{
    const float* x    = (const float*)d_in[0];
    const float* Wq   = (const float*)d_in[1];
    const float* bq   = (const float*)d_in[2];
    const float* Wk   = (const float*)d_in[3];
    const float* bk   = (const float*)d_in[4];
    const float* Wv   = (const float*)d_in[5];
    const float* bv   = (const float*)d_in[6];
    const float* Wp   = (const float*)d_in[7];
    const float* bp   = (const float*)d_in[8];
    const float* sr_w = (const float*)d_in[9];
    const float* sr_b = (const float*)d_in[10];
    const float* ln_g = (const float*)d_in[11];
    const float* ln_b = (const float*)d_in[12];
    float* out = (float*)d_out;

    float *kv, *qb, *kb, *vb, *ab;
    cudaGetSymbolAddress((void**)&kv, g_kv);
    cudaGetSymbolAddress((void**)&qb, g_q);
    cudaGetSymbolAddress((void**)&kb, g_k);
    cudaGetSymbolAddress((void**)&vb, g_v);
    cudaGetSymbolAddress((void**)&ab, g_attn);

    // 1. SR conv (patch GEMM) -> kv_raw
    conv_gemm<<<dim3(4, 64), 256>>>(x, sr_w, sr_b, kv);
    // 2. LayerNorm in place
    ln_kernel<<<BQ * NKV, 256>>>(kv, ln_g, ln_b);
    // 3. Q projection (head-major scatter), fused K+V projection
    gemm_tile<8, 1, 12><<<dim3(4, 128), 256>>>(x,  Wq, Wq, bq, bq, qb, qb, 512);
    gemm_tile<4, 2, 10><<<dim3(8, 64),  256>>>(kv, Wk, Wv, bk, bv, kb, vb, 512);
    // 4. flash attention
    const int fl_smem = FTOT * (int)sizeof(float);
    cudaFuncSetAttribute(flash_kernel,
                         cudaFuncAttributeMaxDynamicSharedMemorySize, fl_smem);
    flash_kernel<<<dim3(NQ / 64, NH, BQ), 128, fl_smem>>>(qb, kb, vb, ab);
    // 5. output projection
    gemm_tile<8, 0, 1><<<dim3(4, 128), 256>>>(ab, Wp, Wp, bp, bp, out, out, 512);
}